// round 1
// baseline (speedup 1.0000x reference)
#include <cuda_runtime.h>

// Net_12403865551680 — 2-layer GCN + mean-pool + Kronecker BN-MLP head.
// Key transform: project-then-aggregate (linearity of segment-mean), so the
// edge scatter runs on 100/20 dims instead of 128/100.

typedef unsigned long long ull;

#define NN 100000
#define NE 1600000
#define NG 1024

// ---------------- scratch (static device allocations) ----------------
__device__ float d_hp1[NN * 100];   // feat@W1, then overwritten by h1
__device__ float d_ms1[NN * 100];   // layer-1 message sums
__device__ float d_hp2[NN * 20];    // h1@W2
__device__ float d_ms2[NN * 20];    // layer-2 message sums
__device__ int   d_deg[NN];
__device__ float d_gsum[NG * 20];
__device__ float d_gcnt[NG];
__device__ float d_hg[NG * 20];
__device__ float d_y1[NG * 128];
__device__ float d_y2[NG * 32];
__device__ float d_stat1[2 * 128];  // mean | rstd
__device__ float d_stat2[2 * 32];

// ---------------- packed f32x2 helpers ----------------
__device__ __forceinline__ ull dup2(float x) {
    ull r; asm("mov.b64 %0, {%1, %1};" : "=l"(r) : "f"(x)); return r;
}
__device__ __forceinline__ void fma2(ull& d, ull a, ull b) {
    asm("fma.rn.f32x2 %0, %1, %2, %0;" : "+l"(d) : "l"(a), "l"(b));
}
__device__ __forceinline__ float f2lo(ull v) { return __uint_as_float((unsigned)v); }
__device__ __forceinline__ float f2hi(ull v) { return __uint_as_float((unsigned)(v >> 32)); }

// ---------------- zero scratch (graph replay must re-zero) ----------------
__global__ void zero_kernel() {
    int i = blockIdx.x * blockDim.x + threadIdx.x;
    int st = gridDim.x * blockDim.x;
    float4 z = make_float4(0.f, 0.f, 0.f, 0.f);
    for (int j = i; j < NN * 100 / 4; j += st) ((float4*)d_ms1)[j] = z;
    for (int j = i; j < NN * 20 / 4;  j += st) ((float4*)d_ms2)[j] = z;
    for (int j = i; j < NN;           j += st) d_deg[j] = 0;
    for (int j = i; j < NG * 20;      j += st) d_gsum[j] = 0.f;
    for (int j = i; j < NG;           j += st) d_gcnt[j] = 0.f;
}

// ---------------- tiled GEMM: Y[M,N] = X[M,K] @ W[K,N], f32x2 packed ----------------
// Thread tile: NPT nodes (as NPT/2 packed pairs) x 4 outputs.
// Xs is stored K-major so node pairs load as a single LDS.64 (no packing).
template<int N, int OT, int NT, int NPT, int KC, int LAYER>
__global__ void __launch_bounds__(OT * NT) proj_kernel(const float* __restrict__ Xin,
                                                       const float* __restrict__ W,
                                                       int M, int K)
{
    const float* __restrict__ X = (LAYER == 1) ? Xin : (const float*)d_hp1;
    float* __restrict__ Y = (LAYER == 1) ? d_hp1 : d_hp2;

    constexpr int NODE_TILE = NT * NPT;
    constexpr int XSS = NODE_TILE + 2;       // even pad: keeps 8B alignment, kills conflicts
    constexpr int NTH = OT * NT;
    __shared__ float Xs[KC * XSS];
    __shared__ float Ws[KC * N];

    const int tid = threadIdx.x;
    const int ot = tid % OT;
    const int nt = tid / OT;
    const int nodeBase = blockIdx.x * NODE_TILE;

    ull acc[NPT / 2][4];
#pragma unroll
    for (int i = 0; i < NPT / 2; i++) { acc[i][0] = 0; acc[i][1] = 0; acc[i][2] = 0; acc[i][3] = 0; }

    for (int kc0 = 0; kc0 < K; kc0 += KC) {
        __syncthreads();
        // load X chunk transposed: Xs[k][n] = X[nodeBase+n][kc0+k]
        for (int idx = tid; idx < KC * NODE_TILE; idx += NTH) {
            int k = idx % KC;
            int n = idx / KC;
            int gn = nodeBase + n;
            float v = (gn < M) ? X[gn * K + kc0 + k] : 0.f;
            Xs[k * XSS + n] = v;
        }
        // load W chunk: Ws[k][o]
        for (int idx = tid; idx < KC * N; idx += NTH) {
            int o = idx % N;
            int k = idx / N;
            Ws[idx] = W[(kc0 + k) * N + o];
        }
        __syncthreads();
#pragma unroll 4
        for (int k = 0; k < KC; k++) {
            float4 wv = *(const float4*)&Ws[k * N + ot * 4];
            ull w0 = dup2(wv.x), w1 = dup2(wv.y), w2 = dup2(wv.z), w3 = dup2(wv.w);
#pragma unroll
            for (int i = 0; i < NPT / 2; i++) {
                ull a = *(const ull*)&Xs[k * XSS + nt * NPT + 2 * i];
                fma2(acc[i][0], a, w0);
                fma2(acc[i][1], a, w1);
                fma2(acc[i][2], a, w2);
                fma2(acc[i][3], a, w3);
            }
        }
    }
#pragma unroll
    for (int i = 0; i < NPT / 2; i++) {
        int n0 = nodeBase + nt * NPT + 2 * i;
        float4 r0 = make_float4(f2lo(acc[i][0]), f2lo(acc[i][1]), f2lo(acc[i][2]), f2lo(acc[i][3]));
        float4 r1 = make_float4(f2hi(acc[i][0]), f2hi(acc[i][1]), f2hi(acc[i][2]), f2hi(acc[i][3]));
        if (n0 < M)     *(float4*)&Y[n0 * N + ot * 4] = r0;
        if (n0 + 1 < M) *(float4*)&Y[(n0 + 1) * N + ot * 4] = r1;
    }
}

// ---------------- degree histogram ----------------
__global__ void deg_kernel(const int* __restrict__ dst, int E) {
    int i = blockIdx.x * blockDim.x + threadIdx.x;
    if (i < E) atomicAdd(&d_deg[dst[i]], 1);
}

// ---------------- edge scatter: msum[dst] += hp[src], vectorized red ----------------
template<int D, int V, int LAYER>
__global__ void scatter_kernel(const int* __restrict__ src, const int* __restrict__ dst, int E) {
    const float* __restrict__ hp = (LAYER == 1) ? (const float*)d_hp1 : (const float*)d_hp2;
    float* __restrict__ ms = (LAYER == 1) ? d_ms1 : d_ms2;
    int i = blockIdx.x * blockDim.x + threadIdx.x;
    if (i >= E * V) return;
    int e = i / V;
    int c = i - e * V;
    int s = src[e];
    int d = dst[e];
    float4 v = *(const float4*)(hp + s * D + c * 4);
    float4* q = (float4*)(ms + d * D + c * 4);
    asm volatile("red.global.add.v4.f32 [%0], {%1,%2,%3,%4};"
                 :: "l"(q), "f"(v.x), "f"(v.y), "f"(v.z), "f"(v.w) : "memory");
}

// ---------------- finish layer 1: h1 = relu(agg + b1), in-place into d_hp1 ----------------
__global__ void finish1_kernel(const float* __restrict__ b1) {
    int i = blockIdx.x * blockDim.x + threadIdx.x;
    if (i >= NN * 100) return;
    int n = i / 100;
    int c = i - n * 100;
    int dg = d_deg[n];
    float v = (dg > 0) ? d_ms1[i] / (float)dg : d_hp1[i];
    d_hp1[i] = fmaxf(v + b1[c], 0.f);
}

// ---------------- finish layer 2 + fused graph pooling ----------------
__global__ void finish2_kernel(const float* __restrict__ b2, const int* __restrict__ n2g) {
    int i = blockIdx.x * blockDim.x + threadIdx.x;
    if (i >= NN * 20) return;
    int n = i / 20;
    int c = i - n * 20;
    int dg = d_deg[n];
    float v = (dg > 0) ? d_ms2[i] / (float)dg : d_hp2[i];
    v = fmaxf(v + b2[c], 0.f);
    int g = n2g[n];
    atomicAdd(&d_gsum[g * 20 + c], v);
    if (c == 0) atomicAdd(&d_gcnt[g], 1.f);
}

__global__ void pooldiv_kernel() {
    int i = blockIdx.x * blockDim.x + threadIdx.x;
    if (i >= NG * 20) return;
    d_hg[i] = d_gsum[i] / fmaxf(d_gcnt[i / 20], 1.f);
}

// ---------------- Kronecker-fused GEMM: y1 = (hg (x) sf) @ Wf1 + bf1 ----------------
__global__ void __launch_bounds__(128) mlp1_kernel(const float* __restrict__ sf,
                                                   const float* __restrict__ Wf1,
                                                   const float* __restrict__ bf1) {
    __shared__ float fs[16 * 640];
    int g0 = blockIdx.x * 16;
    int tid = threadIdx.x;
    for (int idx = tid; idx < 16 * 640; idx += 128) {
        int g = idx / 640;
        int j = idx - g * 640;
        int k = j >> 5, s = j & 31;
        fs[idx] = d_hg[(g0 + g) * 20 + k] * sf[(g0 + g) * 32 + s];
    }
    __syncthreads();
    int o = tid;
    float acc[16];
#pragma unroll
    for (int g = 0; g < 16; g++) acc[g] = 0.f;
    for (int j = 0; j < 640; j++) {
        float w = Wf1[j * 128 + o];
#pragma unroll
        for (int g = 0; g < 16; g++) acc[g] += fs[g * 640 + j] * w;
    }
    float b = bf1[o];
#pragma unroll
    for (int g = 0; g < 16; g++) d_y1[(g0 + g) * 128 + o] = acc[g] + b;
}

// ---------------- BatchNorm stats (biased, training mode) ----------------
template<int C>
__global__ void bnstats_kernel() {
    const float* __restrict__ Y = (C == 128) ? (const float*)d_y1 : (const float*)d_y2;
    float* __restrict__ stat = (C == 128) ? d_stat1 : d_stat2;
    int c = blockIdx.x;
    float s = 0.f, q = 0.f;
    for (int r = threadIdx.x; r < NG; r += 256) {
        float x = Y[r * C + c];
        s += x; q += x * x;
    }
#pragma unroll
    for (int o = 16; o > 0; o >>= 1) {
        s += __shfl_down_sync(0xffffffff, s, o);
        q += __shfl_down_sync(0xffffffff, q, o);
    }
    __shared__ float ss[8], sq[8];
    int w = threadIdx.x >> 5, l = threadIdx.x & 31;
    if (l == 0) { ss[w] = s; sq[w] = q; }
    __syncthreads();
    if (threadIdx.x == 0) {
        float S = 0.f, Q = 0.f;
#pragma unroll
        for (int i = 0; i < 8; i++) { S += ss[i]; Q += sq[i]; }
        float mu = S / (float)NG;
        float var = Q / (float)NG - mu * mu;
        stat[c] = mu;
        stat[C + c] = rsqrtf(var + 1e-5f);
    }
}

// ---------------- y2 = bn_relu(y1) @ Wf2 + bf2 ----------------
__global__ void mlp2_kernel(const float* __restrict__ Wf2, const float* __restrict__ bf2,
                            const float* __restrict__ g1, const float* __restrict__ be1) {
    int i = blockIdx.x * blockDim.x + threadIdx.x;  // 1024*32
    int g = i >> 5, o = i & 31;
    float acc = 0.f;
    for (int k = 0; k < 128; k++) {
        float x = d_y1[g * 128 + k];
        x = fmaxf((x - d_stat1[k]) * d_stat1[128 + k] * g1[k] + be1[k], 0.f);
        acc += x * Wf2[k * 32 + o];
    }
    d_y2[g * 32 + o] = acc + bf2[o];
}

// ---------------- out = bn_relu(y2) @ Wf3 + bf3 ----------------
__global__ void mlp3_kernel(const float* __restrict__ Wf3, const float* __restrict__ bf3,
                            const float* __restrict__ g2, const float* __restrict__ be2,
                            float* __restrict__ out) {
    int i = blockIdx.x * blockDim.x + threadIdx.x;  // 1024*8
    int g = i >> 3, o = i & 7;
    float acc = 0.f;
#pragma unroll
    for (int k = 0; k < 32; k++) {
        float x = d_y2[g * 32 + k];
        x = fmaxf((x - d_stat2[k]) * d_stat2[32 + k] * g2[k] + be2[k], 0.f);
        acc += x * Wf3[k * 8 + o];
    }
    out[i] = acc + bf3[o];
}

extern "C" void kernel_launch(void* const* d_in, const int* in_sizes, int n_in,
                              void* d_out, int out_size) {
    const float* feat = (const float*)d_in[0];
    const float* sf   = (const float*)d_in[1];
    const int*   src  = (const int*)d_in[2];
    const int*   dst  = (const int*)d_in[3];
    const int*   n2g  = (const int*)d_in[4];
    const float* W1   = (const float*)d_in[5];
    const float* b1   = (const float*)d_in[6];
    const float* W2   = (const float*)d_in[7];
    const float* b2   = (const float*)d_in[8];
    const float* Wf1  = (const float*)d_in[9];
    const float* bf1  = (const float*)d_in[10];
    const float* g1   = (const float*)d_in[11];
    const float* be1  = (const float*)d_in[12];
    const float* Wf2  = (const float*)d_in[13];
    const float* bf2  = (const float*)d_in[14];
    const float* g2   = (const float*)d_in[15];
    const float* be2  = (const float*)d_in[16];
    const float* Wf3  = (const float*)d_in[17];
    const float* bf3  = (const float*)d_in[18];
    float* out = (float*)d_out;

    zero_kernel<<<2048, 256>>>();

    // layer 1: project (128->100) then aggregate
    proj_kernel<100, 25, 8, 16, 32, 1><<<(NN + 127) / 128, 25 * 8>>>(feat, W1, NN, 128);
    deg_kernel<<<(NE + 255) / 256, 256>>>(dst, NE);
    scatter_kernel<100, 25, 1><<<(NE * 25 + 255) / 256, 256>>>(src, dst, NE);
    finish1_kernel<<<(NN * 100 + 255) / 256, 256>>>(b1);

    // layer 2: project (100->20) then aggregate, fused pooling
    proj_kernel<20, 5, 32, 16, 20, 2><<<(NN + 511) / 512, 5 * 32>>>(feat, W2, NN, 100);
    scatter_kernel<20, 5, 2><<<(NE * 5 + 255) / 256, 256>>>(src, dst, NE);
    finish2_kernel<<<(NN * 20 + 255) / 256, 256>>>(b2, n2g);
    pooldiv_kernel<<<(NG * 20 + 255) / 256, 256>>>();

    // MLP head
    mlp1_kernel<<<NG / 16, 128>>>(sf, Wf1, bf1);
    bnstats_kernel<128><<<128, 256>>>();
    mlp2_kernel<<<NG * 32 / 256, 256>>>(Wf2, bf2, g1, be1);
    bnstats_kernel<32><<<32, 256>>>();
    mlp3_kernel<<<NG * 8 / 256, 256>>>(Wf3, bf3, g2, be2, out);
}